// round 13
// baseline (speedup 1.0000x reference)
#include <cuda_runtime.h>

// ============================================================================
// AUC_86990267613596 — Round 13 (identical resubmit of the fused R8 design;
// R8-R12 all unbenched: broker timeouts). Single fused kernel (last-block
// finalize + self-reset for graph replay), u16-packed per-(warp,lane)-column
// histogram (4 blocks/SM, 32 warps), explicit LDG prefetch across the RMW chain.
// ============================================================================

#define LUTN   256
#define TPB    256
#define NWARPS 8
#define GRID   592                                   // 148 SMs x 4 blocks
#define HIST_WORDS (NWARPS * 16 * 32)                // 4096 (u32 = 2 x u16 bins)
#define SMEM_BYTES ((LUTN * 32 + HIST_WORDS + 32) * 4)   // 49,280 B

// xt[k] = logit((k+1)/30), k = 0..28 (k=29 -> +inf, handled as NaN sentinel).
__constant__ float c_xt[29] = {
    -3.3672958299864741f, -2.6390572896531649f, -2.1972245773362196f,
    -1.8718021769015914f, -1.6094379124341003f, -1.3862943611198906f,
    -1.1895841068359301f, -1.0116009116784801f, -0.8472978204251098f,
    -0.6931471805599453f, -0.5465437063680696f, -0.4054651081081644f,
    -0.2682639865946793f, -0.1335314325866163f,  0.0f,
     0.1335314325866163f,  0.2682639865946793f,  0.4054651081081644f,
     0.5465437063680696f,  0.6931471805599453f,  0.8472978204251098f,
     1.0116009116784801f,  1.1895841068359301f,  1.3862943611198906f,
     1.6094379124341003f,  1.8718021769015914f,  2.1972245773362196f,
     2.6390572896531649f,  3.3672958299864741f
};

__device__ unsigned g_hist_all[32];   // zero-initialized; finalize re-zeroes
__device__ unsigned g_hist_t[32];
__device__ unsigned g_done;

// Packed-LUT binning: entry = threshold fp32 with low 5 mantissa bits = base bin.
__device__ __forceinline__ unsigned calc_bin(float x, const unsigned* __restrict__ lutl)
{
    float fi = fminf(fmaxf(fmaf(x, 256.0f / 7.0f, 128.0f), 0.0f), 255.0f);
    unsigned e = lutl[(int)fi << 5];               // bank == lane: conflict-free
    return (e & 31u) + ((x >= __uint_as_float(e)) ? 1u : 0u);
}

// u16-packed RMW into own lane column: word pair = b>>1, half = b&1.
__device__ __forceinline__ void hrmw(unsigned b, unsigned* __restrict__ hl)
{
    unsigned inc = (b & 1u) ? 65536u : 1u;
    hl[(b >> 1) << 5] += inc;
}

// ---------------------------------------------------------------------------
__global__ void __launch_bounds__(TPB, 4) auc_fused_kernel(
    const float* __restrict__ outp, const int* __restrict__ target,
    float* __restrict__ out, int total4, int n, int C, int total)
{
    extern __shared__ unsigned smem[];
    unsigned* s_lut  = smem;                        // LUTN*32 words (32 KB)
    unsigned* s_hist = smem + LUTN * 32;            // 8 warps x 16 pairs x 32 lanes
    unsigned* s_ht   = s_hist + HIST_WORDS;         // 32 words

    const int      tid  = threadIdx.x;
    const unsigned lane = tid & 31u;
    const int      wid  = tid >> 5;

    for (int i = tid; i < HIST_WORDS + 32; i += TPB) s_hist[i] = 0u;

    // Build packed LUT cell tid, write 32 swizzled replicas (conflict-free STS).
    {
        float cl = -3.5f + (float)tid * (7.0f / 256.0f);
        int base = 0;
#pragma unroll
        for (int k = 0; k < 29; k++) base += (c_xt[k] <= cl) ? 1 : 0;
        unsigned pb = (base < 29)
            ? ((__float_as_uint(c_xt[base]) & 0xFFFFFFE0u) | (unsigned)base)
            : (0x7F800000u | 29u);                  // NaN: x>=NaN false, bin=29
#pragma unroll
        for (int r = 0; r < 32; r++)
            s_lut[(tid << 5) + ((r + tid) & 31)] = pb;
    }
    __syncthreads();

    const unsigned* __restrict__ lutl = s_lut + lane;
    unsigned* __restrict__ hl = s_hist + (wid << 9) + lane;   // own u16 column

    // ---- True-class pre-pass (scattered gather, ~3.3 rows/thread).
    for (int r = blockIdx.x * TPB + tid; r < n; r += GRID * TPB) {
        const int   t = target[r];
        const float x = outp[r * C + t];
        atomicAdd(&s_ht[calc_bin(x, lutl)], 1u);
    }

    // ---- Main streaming pass: 4 back-to-back LDG.128, software-pipelined so
    // next iteration's loads are in flight during this iteration's RMW chain.
    const float4* __restrict__ out4 = (const float4*)outp;
    const int stride = GRID * TPB;
    int v = blockIdx.x * TPB + tid;
    bool has = (v + 3 * stride < total4);

    float4 dA, dB, dC, dD;
    if (has) {
        dA = out4[v];
        dB = out4[v +     stride];
        dC = out4[v + 2 * stride];
        dD = out4[v + 3 * stride];
    }
    while (has) {
        const int  vn   = v + 4 * stride;
        const bool hasn = (vn + 3 * stride < total4);

        // Compute all 16 bins (independent; LUT LDS pipelined).
        unsigned b[16];
        b[0]  = calc_bin(dA.x, lutl); b[1]  = calc_bin(dA.y, lutl);
        b[2]  = calc_bin(dA.z, lutl); b[3]  = calc_bin(dA.w, lutl);
        b[4]  = calc_bin(dB.x, lutl); b[5]  = calc_bin(dB.y, lutl);
        b[6]  = calc_bin(dB.z, lutl); b[7]  = calc_bin(dB.w, lutl);
        b[8]  = calc_bin(dC.x, lutl); b[9]  = calc_bin(dC.y, lutl);
        b[10] = calc_bin(dC.z, lutl); b[11] = calc_bin(dC.w, lutl);
        b[12] = calc_bin(dD.x, lutl); b[13] = calc_bin(dD.y, lutl);
        b[14] = calc_bin(dD.z, lutl); b[15] = calc_bin(dD.w, lutl);

        // Prefetch next iteration (LDG; cannot alias the STS below).
        if (hasn) {
            dA = out4[vn];
            dB = out4[vn +     stride];
            dC = out4[vn + 2 * stride];
            dD = out4[vn + 3 * stride];
        }

        // RMW chain (serialized by potential same-address dependencies).
#pragma unroll
        for (int j = 0; j < 16; j++) hrmw(b[j], hl);

        v = vn; has = hasn;
    }
    for (; v < total4; v += stride) {               // tail: <= 3 float4s
        const float4 d = out4[v];
        hrmw(calc_bin(d.x, lutl), hl);
        hrmw(calc_bin(d.y, lutl), hl);
        hrmw(calc_bin(d.z, lutl), hl);
        hrmw(calc_bin(d.w, lutl), hl);
    }

    __syncthreads();

    // ---- Block reduction: thread (w=wid, bin=lane) sums its warp's bin over
    // 32 lane columns (swizzled, conflict-free), then atomics to global.
    {
        const unsigned* row = s_hist + (wid << 9) + (((int)lane >> 1) << 5);
        const unsigned  sh  = (lane & 1u) << 4;
        unsigned sum = 0;
#pragma unroll
        for (int j = 0; j < 32; j++)
            sum += (row[(j + lane) & 31] >> sh) & 0xFFFFu;
        if (sum) atomicAdd(&g_hist_all[lane], sum);
    }
    if (tid < 32) {
        unsigned t = s_ht[tid];
        if (t) atomicAdd(&g_hist_t[tid], t);
    }

    // ---- Last-block finalize (ticket), then reset globals for next replay.
    __syncthreads();
    if (tid == 0) {
        __threadfence();
        unsigned ticket = atomicAdd(&g_done, 1u);
        if (ticket == GRID - 1) {
            __threadfence();
            volatile unsigned* vha = g_hist_all;
            volatile unsigned* vht = g_hist_t;

            double t[31], a[31], trues = 0.0;
#pragma unroll 1
            for (int b = 0; b < 31; b++) {
                t[b] = (double)vht[b];
                a[b] = (double)vha[b];
                trues += t[b];
            }
            const double falses = (double)total - trues;

            double tp_asc[30], fp_asc[30];
            double ct = 0.0, cf = 0.0;
#pragma unroll 1
            for (int k = 0; k < 30; k++) {
                ct += t[k];
                cf += (a[k] - t[k]);
                tp_asc[k] = trues  - ct;
                fp_asc[k] = falses - cf;
            }

            const double dt = trues  + 1e-8;
            const double df = falses + 1e-8;
            double area = 0.0, pt = 0.0, pf = 0.0;
#pragma unroll 1
            for (int i = 0; i < 30; i++) {
                const double tt = tp_asc[29 - i] / dt;
                const double ff = fp_asc[29 - i] / df;
                const double w  = fabs(ff - pf);
                const double mn = fmin(tt, pt);
                const double mx = fmax(tt, pt);
                area += w * mn + 0.5 * w * (mx - mn);
                pt = tt; pf = ff;
            }
            out[0] = (float)area;

            // Reset for next graph replay.
#pragma unroll
            for (int b = 0; b < 32; b++) { vha[b] = 0u; vht[b] = 0u; }
            __threadfence();
            g_done = 0u;
        }
    }
}

// ---------------------------------------------------------------------------
extern "C" void kernel_launch(void* const* d_in, const int* in_sizes, int n_in,
                              void* d_out, int out_size) {
    const float* outp   = (const float*)d_in[0];
    const int*   target = (const int*)d_in[1];
    const int total  = in_sizes[0];      // N*C = 32,000,000
    const int n      = in_sizes[1];      // N   = 500,000
    const int C      = total / n;        // 64
    const int total4 = total / 4;

    cudaFuncSetAttribute(auc_fused_kernel,
                         cudaFuncAttributeMaxDynamicSharedMemorySize, SMEM_BYTES);

    auc_fused_kernel<<<GRID, TPB, SMEM_BYTES>>>(outp, target, (float*)d_out,
                                                total4, n, C, total);
}

// round 14
// speedup vs baseline: 1.1944x; 1.1944x over previous
#include <cuda_runtime.h>

// ============================================================================
// AUC_86990267613596 — Round 14: LUT-free arithmetic binning.
// bin = trunc(30 / (1 + e^-x)) via 2 MUFU ops — no LUT smem, no LUT LDS,
// no threshold compare. u32 per-(warp,lane)-column histogram (reverted from
// u16: measured slower), 40 warps/SM (5 blocks x 32.9KB smem), fused
// single-launch with last-block finalize + self-reset.
// ============================================================================

#define TPB    256
#define NWARPS 8
#define BPSM   5
#define GRID   (148 * BPSM)                          // 740
#define HIST_WORDS (NWARPS * 32 * 32)                // 8192 words = 32 KB
#define SMEM_BYTES ((HIST_WORDS + 32) * 4)           // 32,896 B

__device__ unsigned g_hist_all[32];   // zero-init; finalize re-zeroes
__device__ unsigned g_hist_t[32];
__device__ unsigned g_done;

// Arithmetic binning: bin = #(logit((k+1)/30) <= x) = trunc(30*sigmoid(x)).
// 2 MUFU (EX2, RCP) + FMUL/FADD/FMUL/F2I. Exact-saturation semantics match
// the reference (bin 30 iff sigmoid rounds to 1.0, impossible for |x|<16).
__device__ __forceinline__ unsigned calc_bin(float x)
{
    float v   = __expf(-x);                   // FMUL + MUFU.EX2
    float s30 = __fdividef(30.0f, 1.0f + v);  // FADD + MUFU.RCP + FMUL
    return (unsigned)(int)s30;                // F2I.TRUNC, 0..30
}

// u32 RMW into this thread's private lane column (bank == lane, conflict-free).
__device__ __forceinline__ void proc4(float4 d, unsigned* __restrict__ hl)
{
    unsigned b0 = calc_bin(d.x);
    unsigned b1 = calc_bin(d.y);
    unsigned b2 = calc_bin(d.z);
    unsigned b3 = calc_bin(d.w);
    hl[b0 << 5] += 1u;
    hl[b1 << 5] += 1u;
    hl[b2 << 5] += 1u;
    hl[b3 << 5] += 1u;
}

// ---------------------------------------------------------------------------
__global__ void __launch_bounds__(TPB, BPSM) auc_fused_kernel(
    const float* __restrict__ outp, const int* __restrict__ target,
    float* __restrict__ out, int total4, int n, int C, int total)
{
    extern __shared__ unsigned smem[];
    unsigned* s_hist = smem;                 // 8 warps x 32 bins x 32 lanes
    unsigned* s_ht   = smem + HIST_WORDS;    // 32 words

    const int      tid  = threadIdx.x;
    const unsigned lane = tid & 31u;
    const int      wid  = tid >> 5;

    for (int i = tid; i < HIST_WORDS + 32; i += TPB) s_hist[i] = 0u;
    __syncthreads();

    unsigned* __restrict__ hl = s_hist + (wid << 10) + lane;   // own column

    // ---- True-class pre-pass (scattered gather, ~2.6 rows/thread).
    for (int r = blockIdx.x * TPB + tid; r < n; r += GRID * TPB) {
        const int   t = target[r];
        const float x = outp[r * C + t];
        atomicAdd(&s_ht[calc_bin(x)], 1u);
    }

    // ---- Main streaming pass: 4 back-to-back LDG.128 per iteration.
    const float4* __restrict__ out4 = (const float4*)outp;
    const int S = GRID * TPB;
    int v = blockIdx.x * TPB + tid;

    for (; v + 3 * S < total4; v += 4 * S) {
        const float4 dA = out4[v];
        const float4 dB = out4[v +     S];
        const float4 dC = out4[v + 2 * S];
        const float4 dD = out4[v + 3 * S];
        proc4(dA, hl);
        proc4(dB, hl);
        proc4(dC, hl);
        proc4(dD, hl);
    }
    for (; v < total4; v += S)                     // tail: <= 3 float4s
        proc4(out4[v], hl);

    __syncthreads();

    // ---- Block reduction: thread (w=wid, bin=lane) sums its warp's bin over
    // 32 lane columns (swizzled, conflict-free), then atomics to global.
    {
        const unsigned* row = s_hist + (wid << 10) + ((int)lane << 5);
        unsigned sum = 0;
#pragma unroll
        for (int j = 0; j < 32; j++) sum += row[(j + lane) & 31];
        if (sum) atomicAdd(&g_hist_all[lane], sum);
    }
    if (tid < 32) {
        unsigned t = s_ht[tid];
        if (t) atomicAdd(&g_hist_t[tid], t);
    }

    // ---- Last-block finalize (ticket), then reset globals for next replay.
    __syncthreads();
    if (tid == 0) {
        __threadfence();
        unsigned ticket = atomicAdd(&g_done, 1u);
        if (ticket == GRID - 1) {
            __threadfence();
            volatile unsigned* vha = g_hist_all;
            volatile unsigned* vht = g_hist_t;

            double t[31], a[31], trues = 0.0;
#pragma unroll 1
            for (int b = 0; b < 31; b++) {
                t[b] = (double)vht[b];
                a[b] = (double)vha[b];
                trues += t[b];
            }
            const double falses = (double)total - trues;

            double tp_asc[30], fp_asc[30];
            double ct = 0.0, cf = 0.0;
#pragma unroll 1
            for (int k = 0; k < 30; k++) {
                ct += t[k];
                cf += (a[k] - t[k]);
                tp_asc[k] = trues  - ct;
                fp_asc[k] = falses - cf;
            }

            const double dt = trues  + 1e-8;
            const double df = falses + 1e-8;
            double area = 0.0, pt = 0.0, pf = 0.0;
#pragma unroll 1
            for (int i = 0; i < 30; i++) {
                const double tt = tp_asc[29 - i] / dt;
                const double ff = fp_asc[29 - i] / df;
                const double w  = fabs(ff - pf);
                const double mn = fmin(tt, pt);
                const double mx = fmax(tt, pt);
                area += w * mn + 0.5 * w * (mx - mn);
                pt = tt; pf = ff;
            }
            out[0] = (float)area;

            // Reset for next graph replay.
#pragma unroll
            for (int b = 0; b < 32; b++) { vha[b] = 0u; vht[b] = 0u; }
            __threadfence();
            g_done = 0u;
        }
    }
}

// ---------------------------------------------------------------------------
extern "C" void kernel_launch(void* const* d_in, const int* in_sizes, int n_in,
                              void* d_out, int out_size) {
    const float* outp   = (const float*)d_in[0];
    const int*   target = (const int*)d_in[1];
    const int total  = in_sizes[0];      // N*C = 32,000,000
    const int n      = in_sizes[1];      // N   = 500,000
    const int C      = total / n;        // 64
    const int total4 = total / 4;

    cudaFuncSetAttribute(auc_fused_kernel,
                         cudaFuncAttributeMaxDynamicSharedMemorySize, SMEM_BYTES);

    auc_fused_kernel<<<GRID, TPB, SMEM_BYTES>>>(outp, target, (float*)d_out,
                                                total4, n, C, total);
}